// round 8
// baseline (speedup 1.0000x reference)
#include <cuda_runtime.h>
#include <cuda_bf16.h>
#include <math.h>
#include <stdint.h>

// ---------------- static scratch (no allocations allowed) ----------------
#define MAXN 204800
#define MAXB 64

__device__ int    g_warm_idx[MAXN];
__device__ int    g_cold_idx[MAXN];
__device__ int    g_nwarm;
__device__ int    g_ncold;
__device__ double g_kl_sum;
__device__ float  g_sim[(size_t)MAXB * MAXN];
__device__ float  g_qn[MAXB * 256];
__device__ int    g_topidx[MAXB * 32];
// pre-converted weights (hi/lo split), [n][k] row-major
__device__ __nv_bfloat16 g_Wh[256 * 256];  // rows 0-127 = W_mu, 128-255 = W_lv
__device__ __nv_bfloat16 g_Wl[256 * 256];
__device__ __nv_bfloat16 g_Dh[256 * 128];  // W_dec
__device__ __nv_bfloat16 g_Dl[256 * 128];

// ---------------- helpers ----------------
__device__ __forceinline__ uint32_t pk2(__nv_bfloat16 a, __nv_bfloat16 b) {
    return (uint32_t)__bfloat16_as_ushort(a) | ((uint32_t)__bfloat16_as_ushort(b) << 16);
}
__device__ __forceinline__ uint32_t smem_u32(const void* p) {
    uint32_t a;
    asm("{ .reg .u64 t; cvta.to.shared.u64 t, %1; cvt.u32.u64 %0, t; }" : "=r"(a) : "l"(p));
    return a;
}

#define MMA16816(c, a, b) asm volatile( \
    "mma.sync.aligned.m16n8k16.row.col.f32.bf16.bf16.f32 " \
    "{%0,%1,%2,%3}, {%4,%5,%6,%7}, {%8,%9}, {%0,%1,%2,%3};" \
    : "+f"((c)[0]), "+f"((c)[1]), "+f"((c)[2]), "+f"((c)[3]) \
    : "r"((a)[0]), "r"((a)[1]), "r"((a)[2]), "r"((a)[3]), "r"((b)[0]), "r"((b)[1]))

__device__ __forceinline__ void ldm4(uint32_t addr, uint32_t r[4]) {
    asm volatile("ldmatrix.sync.aligned.m8n8.x4.shared.b16 {%0,%1,%2,%3}, [%4];"
                 : "=r"(r[0]), "=r"(r[1]), "=r"(r[2]), "=r"(r[3]) : "r"(addr));
}

// smem layout for k_warm (bytes)
#define TSTRIDE 72           // A/B tile stride in bf16
#define MUSTRIDE 136         // mu tile stride in bf16 (128 cols + pad)
#define OFF_AH  0
#define OFF_AL  18432
#define OFF_BH  36864
#define OFF_BL  73728
#define OFF_MUH 110592
#define OFF_MUL 145408
#define DSMEM_SZ 180224

// split fp32x4 -> bf16 hi/lo, store 8B each into [m][k..k+3]
__device__ __forceinline__ void split_store4(char* smem, int m, int k, float4 v,
                                             int off_hi, int off_lo) {
    __nv_bfloat16 h0 = __float2bfloat16(v.x), h1 = __float2bfloat16(v.y);
    __nv_bfloat16 h2 = __float2bfloat16(v.z), h3 = __float2bfloat16(v.w);
    float l0 = v.x - __bfloat162float(h0), l1 = v.y - __bfloat162float(h1);
    float l2 = v.z - __bfloat162float(h2), l3 = v.w - __bfloat162float(h3);
    size_t base = (size_t)m * TSTRIDE + k;
    *(uint2*)(smem + off_hi + base * 2) = make_uint2(pk2(h0, h1), pk2(h2, h3));
    *(uint2*)(smem + off_lo + base * 2) =
        make_uint2(pk2(__float2bfloat16(l0), __float2bfloat16(l1)),
                   pk2(__float2bfloat16(l2), __float2bfloat16(l3)));
}

// ---------------- small kernels ----------------
__global__ void k_init() { g_nwarm = 0; g_ncold = 0; g_kl_sum = 0.0; }

// warp-aggregated compaction: one atomic per warp per tier instead of one
// per thread (same-address atomicAdd-with-return serializes at the LTS).
__global__ void k_partition(const int* __restrict__ tiers, int N) {
    int i = blockIdx.x * blockDim.x + threadIdx.x;
    bool in = i < N;
    int t = in ? tiers[i] : 0;
    unsigned m1 = __ballot_sync(0xffffffffu, t == 1);
    unsigned m2 = __ballot_sync(0xffffffffu, t == 2);
    int lane = threadIdx.x & 31;
    unsigned lt = (1u << lane) - 1u;
    if (t == 1) {
        int ldr = __ffs(m1) - 1;
        int base = 0;
        if (lane == ldr) base = atomicAdd(&g_nwarm, __popc(m1));
        base = __shfl_sync(m1, base, ldr);
        g_warm_idx[base + __popc(m1 & lt)] = i;
    } else if (t == 2) {
        int ldr = __ffs(m2) - 1;
        int base = 0;
        if (lane == ldr) base = atomicAdd(&g_ncold, __popc(m2));
        base = __shfl_sync(m2, base, ldr);
        g_cold_idx[base + __popc(m2 & lt)] = i;
    }
}

// pre-convert weights to split bf16 (once per launch)
__global__ __launch_bounds__(256) void k_wprep(const float* __restrict__ W_mu,
                                               const float* __restrict__ W_lv,
                                               const float* __restrict__ W_dec) {
    int idx = blockIdx.x * blockDim.x + threadIdx.x;
    if (idx < 65536) {
        int n = idx >> 8, k = idx & 255;
        float w = (n < 128) ? W_mu[(size_t)n * 256 + k] : W_lv[(size_t)(n - 128) * 256 + k];
        __nv_bfloat16 h = __float2bfloat16(w);
        g_Wh[idx] = h;
        g_Wl[idx] = __float2bfloat16(w - __bfloat162float(h));
    } else if (idx < 65536 + 32768) {
        int j = idx - 65536;
        float w = W_dec[j];
        __nv_bfloat16 h = __float2bfloat16(w);
        g_Dh[j] = h;
        g_Dl[j] = __float2bfloat16(w - __bfloat162float(h));
    }
}

// copy new_features = node_features, skipping warm rows (k_warm writes them)
__global__ void k_copy4(const float4* __restrict__ src, float4* __restrict__ dst,
                        const int* __restrict__ tiers, long n4) {
    long i = (long)blockIdx.x * blockDim.x + threadIdx.x;
    if (i >= n4) return;
    int row = (int)(i >> 6);
    if (tiers[row] != 1) dst[i] = src[i];
}

__global__ __launch_bounds__(256) void k_qnorm(const float* __restrict__ q, int D) {
    int b = blockIdx.x, t = threadIdx.x;
    float ss = 0.f;
    for (int c = t; c < D; c += 256) { float v = q[(size_t)b * D + c]; ss += v * v; }
    __shared__ float red[256];
    red[t] = ss; __syncthreads();
    for (int s = 128; s > 0; s >>= 1) { if (t < s) red[t] += red[t + s]; __syncthreads(); }
    float scale = 1.f / (sqrtf(red[0]) + 1e-10f);
    for (int c = t; c < D; c += 256) g_qn[(size_t)b * D + c] = q[(size_t)b * D + c] * scale;
}

__global__ void k_klfin(float* klout, int W) {
    int n = g_nwarm > 0 ? g_nwarm : 1;
    *klout = (float)(g_kl_sum / ((double)n * (double)W));
}

// ---------------- fused warm pipeline: [mu|lv] GEMM + KL + decoder ---------
// Phase 1: [mu|lv](128x256) = X_warm @ [Wmu;Wlv]^T. mu cols (warps wn<2):
//   3-pass hi/lo split; lv cols (wn>=2): single-pass bf16 (KL-mean tolerant).
// Phase 2: dec = mu @ Wdec^T from SMEM mu tiles; scatter to new_features.
__global__ __launch_bounds__(512)
void k_warm(const float* __restrict__ feats,
            const float* __restrict__ b_mu, const float* __restrict__ b_lv,
            const float* __restrict__ b_dec, float* __restrict__ newf) {
    extern __shared__ char smem[];
    const int M = g_nwarm;
    const int m0 = blockIdx.x * 128;
    if (m0 >= M) return;

    const int tid = threadIdx.x, wid = tid >> 5, lane = tid & 31;
    const int wm = wid >> 2, wn = wid & 3;  // warp tile: 32 rows x 64 cols
    const bool is_mu_warp = (wn < 2);
    const uint32_t sb = smem_u32(smem);

    float acc[2][8][4];
    #pragma unroll
    for (int mi = 0; mi < 2; mi++)
        #pragma unroll
        for (int ni = 0; ni < 8; ni++)
            #pragma unroll
            for (int j = 0; j < 4; j++) acc[mi][ni][j] = 0.f;

    const int aRow = (lane & 15), aColSel = (lane >> 4) << 3;
    const int bRow = (lane & 7) + ((lane & 16) >> 1), bColSel = lane & 8;
    const int gq = lane >> 2, qq = (lane & 3) * 2;

    // hoist warm-row gather indices (invariant across K chunks)
    int arows[4];
    #pragma unroll
    for (int it = 0; it < 4; it++) {
        int id = tid + it * 512;
        int r = m0 + (id >> 4);
        arows[it] = g_warm_idx[(r < M) ? r : m0];
    }

    // ===== phase 1: [mu|lv] with A-chunk register prefetch =====
    float4 pf[4];
    #pragma unroll
    for (int it = 0; it < 4; it++) {
        int kq = (tid + it * 512) & 15;
        pf[it] = *(const float4*)(feats + (size_t)arows[it] * 256 + kq * 4);
    }

    for (int c = 0; c < 4; c++) {
        const int k0 = c * 64;
        #pragma unroll
        for (int it = 0; it < 4; it++) {
            int id = tid + it * 512;
            split_store4(smem, id >> 4, (id & 15) * 4, pf[it], OFF_AH, OFF_AL);
        }
        #pragma unroll
        for (int it = 0; it < 4; it++) {
            int id = tid + it * 512;
            int n = id >> 3, q = id & 7;
            size_t src = (size_t)n * 256 + k0 + q * 8;
            size_t dst = ((size_t)n * TSTRIDE + q * 8) * 2;
            *(uint4*)(smem + OFF_BH + dst) = *(const uint4*)(g_Wh + src);
            *(uint4*)(smem + OFF_BL + dst) = *(const uint4*)(g_Wl + src);
        }
        __syncthreads();

        if (c < 3) {
            #pragma unroll
            for (int it = 0; it < 4; it++) {
                int kq = (tid + it * 512) & 15;
                pf[it] = *(const float4*)(feats + (size_t)arows[it] * 256 + (c + 1) * 64 + kq * 4);
            }
        }

        #pragma unroll
        for (int kk = 0; kk < 64; kk += 16) {
            uint32_t ah[2][4], al[2][4];
            #pragma unroll
            for (int mi = 0; mi < 2; mi++) {
                uint32_t off = ((uint32_t)(wm * 32 + mi * 16 + aRow) * TSTRIDE + kk + aColSel) * 2;
                ldm4(sb + OFF_AH + off, ah[mi]);
                if (is_mu_warp) ldm4(sb + OFF_AL + off, al[mi]);
            }
            #pragma unroll
            for (int np = 0; np < 4; np++) {
                int n0 = wn * 64 + np * 16;
                uint32_t boff = ((uint32_t)(n0 + bRow) * TSTRIDE + kk + bColSel) * 2;
                uint32_t bh[4], bl[4];
                ldm4(sb + OFF_BH + boff, bh);
                if (is_mu_warp) ldm4(sb + OFF_BL + boff, bl);
                #pragma unroll
                for (int mi = 0; mi < 2; mi++) {
                    MMA16816(acc[mi][np * 2],     ah[mi], &bh[0]);
                    MMA16816(acc[mi][np * 2 + 1], ah[mi], &bh[2]);
                    if (is_mu_warp) {
                        MMA16816(acc[mi][np * 2],     al[mi], &bh[0]);
                        MMA16816(acc[mi][np * 2],     ah[mi], &bl[0]);
                        MMA16816(acc[mi][np * 2 + 1], al[mi], &bh[2]);
                        MMA16816(acc[mi][np * 2 + 1], ah[mi], &bl[2]);
                    }
                }
            }
        }
        __syncthreads();
    }

    // ===== epilogue 1: KL + mu -> smem (split bf16) =====
    float kl = 0.f;
    #pragma unroll
    for (int mi = 0; mi < 2; mi++) {
        #pragma unroll
        for (int half = 0; half < 2; half++) {
            int rl = wm * 32 + mi * 16 + gq + half * 8;
            int grow = m0 + rl;
            bool valid = grow < M;
            #pragma unroll
            for (int ni = 0; ni < 8; ni++) {
                int col = wn * 64 + ni * 8 + qq;
                int is_lv = col >> 7;
                int cl = col & 127;
                float bias0 = is_lv ? b_lv[cl] : b_mu[cl];
                float bias1 = is_lv ? b_lv[cl + 1] : b_mu[cl + 1];
                float v0 = acc[mi][ni][half * 2 + 0] + bias0;
                float v1 = acc[mi][ni][half * 2 + 1] + bias1;
                if (!is_lv) {
                    __nv_bfloat16 h0 = __float2bfloat16(v0), h1 = __float2bfloat16(v1);
                    float l0 = v0 - __bfloat162float(h0), l1 = v1 - __bfloat162float(h1);
                    uint32_t o = ((uint32_t)rl * MUSTRIDE + cl) * 2;
                    *(uint32_t*)(smem + OFF_MUH + o) = pk2(h0, h1);
                    *(uint32_t*)(smem + OFF_MUL + o) = pk2(__float2bfloat16(l0), __float2bfloat16(l1));
                    if (valid) kl += 0.5f * (v0 * v0 + v1 * v1) - 1.0f;
                } else if (valid) {
                    kl += 0.5f * (expf(v0) + expf(v1)) - 0.5f * (v0 + v1);
                }
            }
        }
    }
    #pragma unroll
    for (int o = 16; o > 0; o >>= 1) kl += __shfl_xor_sync(0xffffffffu, kl, o);
    if (lane == 0 && kl != 0.f) atomicAdd(&g_kl_sum, (double)kl);
    __syncthreads();

    // ===== phase 2: dec = mu @ Wdec^T =====
    #pragma unroll
    for (int mi = 0; mi < 2; mi++)
        #pragma unroll
        for (int ni = 0; ni < 8; ni++)
            #pragma unroll
            for (int j = 0; j < 4; j++) acc[mi][ni][j] = 0.f;

    for (int c = 0; c < 2; c++) {
        const int k0 = c * 64;
        #pragma unroll
        for (int it = 0; it < 4; it++) {
            int id = tid + it * 512;
            int n = id >> 3, q = id & 7;
            size_t src = (size_t)n * 128 + k0 + q * 8;
            size_t dst = ((size_t)n * TSTRIDE + q * 8) * 2;
            *(uint4*)(smem + OFF_BH + dst) = *(const uint4*)(g_Dh + src);
            *(uint4*)(smem + OFF_BL + dst) = *(const uint4*)(g_Dl + src);
        }
        __syncthreads();

        #pragma unroll
        for (int kk = 0; kk < 64; kk += 16) {
            uint32_t ah[2][4], al[2][4];
            #pragma unroll
            for (int mi = 0; mi < 2; mi++) {
                uint32_t off = ((uint32_t)(wm * 32 + mi * 16 + aRow) * MUSTRIDE + k0 + kk + aColSel) * 2;
                ldm4(sb + OFF_MUH + off, ah[mi]);
                ldm4(sb + OFF_MUL + off, al[mi]);
            }
            #pragma unroll
            for (int np = 0; np < 4; np++) {
                int n0 = wn * 64 + np * 16;
                uint32_t boff = ((uint32_t)(n0 + bRow) * TSTRIDE + kk + bColSel) * 2;
                uint32_t bh[4], bl[4];
                ldm4(sb + OFF_BH + boff, bh);
                ldm4(sb + OFF_BL + boff, bl);
                #pragma unroll
                for (int mi = 0; mi < 2; mi++) {
                    MMA16816(acc[mi][np * 2],     ah[mi], &bh[0]);
                    MMA16816(acc[mi][np * 2],     al[mi], &bh[0]);
                    MMA16816(acc[mi][np * 2],     ah[mi], &bl[0]);
                    MMA16816(acc[mi][np * 2 + 1], ah[mi], &bh[2]);
                    MMA16816(acc[mi][np * 2 + 1], al[mi], &bh[2]);
                    MMA16816(acc[mi][np * 2 + 1], ah[mi], &bl[2]);
                }
            }
        }
        __syncthreads();
    }

    // ===== epilogue 2: scatter dec to warm rows =====
    #pragma unroll
    for (int mi = 0; mi < 2; mi++) {
        #pragma unroll
        for (int half = 0; half < 2; half++) {
            int grow = m0 + wm * 32 + mi * 16 + gq + half * 8;
            if (grow >= M) continue;
            int wr = g_warm_idx[grow];
            #pragma unroll
            for (int ni = 0; ni < 8; ni++) {
                int col = wn * 64 + ni * 8 + qq;
                float2 v = make_float2(acc[mi][ni][half * 2 + 0] + b_dec[col],
                                       acc[mi][ni][half * 2 + 1] + b_dec[col + 1]);
                *(float2*)(newf + (size_t)wr * 256 + col) = v;
            }
        }
    }
}

// ---------------- sim GEMM (fp32 SIMT; fused row norms) -------------------
__global__ __launch_bounds__(256) void k_sim(const float* __restrict__ feats, int D, int simld) {
    const int M = g_ncold;
    const int m0 = blockIdx.x * 128;
    if (m0 >= M) return;

    __shared__ float Xs[16][128];
    __shared__ float Qs[16][64];

    const int tid = threadIdx.x;
    const int ty = tid >> 4, tx = tid & 15;

    float acc[8][4];
    float ssq[8];
    #pragma unroll
    for (int i = 0; i < 8; i++) {
        ssq[i] = 0.f;
        #pragma unroll
        for (int j = 0; j < 4; j++) acc[i][j] = 0.f;
    }

    for (int k0 = 0; k0 < D; k0 += 16) {
        #pragma unroll
        for (int i = 0; i < 2; i++) {
            int id = tid + i * 256;
            int m = id & 127, kq = id >> 7;
            int r = m0 + m;
            int arow = (r < M) ? g_cold_idx[r] : g_cold_idx[m0];
            float4 v = *(const float4*)(feats + (size_t)arow * D + k0 + kq * 4);
            Xs[kq * 4 + 0][m] = v.x; Xs[kq * 4 + 1][m] = v.y;
            Xs[kq * 4 + 2][m] = v.z; Xs[kq * 4 + 3][m] = v.w;
        }
        {
            int q = tid & 63, kq = tid >> 6;
            float4 v = *(const float4*)(g_qn + (size_t)q * D + k0 + kq * 4);
            Qs[kq * 4 + 0][q] = v.x; Qs[kq * 4 + 1][q] = v.y;
            Qs[kq * 4 + 2][q] = v.z; Qs[kq * 4 + 3][q] = v.w;
        }
        __syncthreads();
        #pragma unroll
        for (int kk = 0; kk < 16; kk++) {
            float4 a0 = *(const float4*)&Xs[kk][ty * 4];
            float4 a1 = *(const float4*)&Xs[kk][ty * 4 + 64];
            float4 b0 = *(const float4*)&Qs[kk][tx * 4];
            float a[8] = {a0.x, a0.y, a0.z, a0.w, a1.x, a1.y, a1.z, a1.w};
            float b[4] = {b0.x, b0.y, b0.z, b0.w};
            #pragma unroll
            for (int i = 0; i < 8; i++) {
                ssq[i] += a[i] * a[i];
                #pragma unroll
                for (int j = 0; j < 4; j++) acc[i][j] += a[i] * b[j];
            }
        }
        __syncthreads();
    }

    #pragma unroll
    for (int i = 0; i < 8; i++) {
        int rl = (i < 4) ? (ty * 4 + i) : (64 + ty * 4 + i - 4);
        int j = m0 + rl;
        if (j < M) {
            float inv = 1.f / (sqrtf(ssq[i]) + 1e-10f);
            #pragma unroll
            for (int jj = 0; jj < 4; jj++) {
                int q = tx * 4 + jj;
                g_sim[(size_t)q * simld + j] = acc[i][jj] * inv;
            }
        }
    }
}

// ---------------- top-k (value desc, index asc tie-break) ------------------
__global__ __launch_bounds__(256) void k_topk(int simld, int k, float* __restrict__ out_idx_f) {
    const int b = blockIdx.x;
    const int ncold = g_ncold;
    const int t = threadIdx.x;

    float lv[16]; int li[16];
    #pragma unroll
    for (int s = 0; s < 16; s++) { lv[s] = -INFINITY; li[s] = 0x7fffffff; }

    const float* srow = g_sim + (size_t)b * simld;
    for (int j = t; j < ncold; j += 256) {
        float v = srow[j];
        int gi = g_cold_idx[j];
        if (v > lv[0] || (v == lv[0] && gi < li[0])) {
            lv[0] = v; li[0] = gi;
            #pragma unroll
            for (int s = 0; s < 15; s++) {
                bool sw = (lv[s] > lv[s + 1]) || (lv[s] == lv[s + 1] && li[s] < li[s + 1]);
                if (sw) {
                    float tv = lv[s]; lv[s] = lv[s + 1]; lv[s + 1] = tv;
                    int ti = li[s]; li[s] = li[s + 1]; li[s + 1] = ti;
                }
            }
        }
    }

    __shared__ float sval[4096];
    __shared__ int   sidxs[4096];
    __shared__ float rv[256];
    __shared__ int   ri[256];
    __shared__ int   rp[256];

    #pragma unroll
    for (int s = 0; s < 16; s++) { sval[t * 16 + s] = lv[s]; sidxs[t * 16 + s] = li[s]; }
    __syncthreads();

    for (int sel = 0; sel < k; sel++) {
        float bv = -INFINITY; int bi = 0x7fffffff; int bp = -1;
        for (int p = t; p < 4096; p += 256) {
            float v = sval[p]; int gi = sidxs[p];
            if (v > bv || (v == bv && gi < bi)) { bv = v; bi = gi; bp = p; }
        }
        rv[t] = bv; ri[t] = bi; rp[t] = bp;
        __syncthreads();
        for (int s = 128; s > 0; s >>= 1) {
            if (t < s) {
                if (rv[t + s] > rv[t] || (rv[t + s] == rv[t] && ri[t + s] < ri[t])) {
                    rv[t] = rv[t + s]; ri[t] = ri[t + s]; rp[t] = rp[t + s];
                }
            }
            __syncthreads();
        }
        if (t == 0) {
            g_topidx[b * 32 + sel] = ri[0];
            out_idx_f[(size_t)b * k + sel] = (float)ri[0];
            if (rp[0] >= 0) { sval[rp[0]] = -INFINITY; sidxs[rp[0]] = 0x7fffffff; }
        }
        __syncthreads();
    }
}

// Scalar stores: ret base is d_out + N*D + 1 floats (only 4B aligned).
__global__ __launch_bounds__(256) void k_gather(const float* __restrict__ newf,
                                                float* __restrict__ ret, int D, int k) {
    int r = blockIdx.x;
    int row = g_topidx[(r / k) * 32 + (r % k)];
    const float* s = newf + (size_t)row * D;
    float* d = ret + (size_t)r * D;
    for (int c = threadIdx.x; c < D; c += blockDim.x) d[c] = s[c];
}

extern "C" void kernel_launch(void* const* d_in, const int* in_sizes, int n_in,
                              void* d_out, int out_size) {
    const float* feats = (const float*)d_in[0];
    const int*   tiers = (const int*)d_in[1];
    const float* query = (const float*)d_in[2];
    const float* W_mu  = (const float*)d_in[3];
    const float* b_mu  = (const float*)d_in[4];
    const float* W_lv  = (const float*)d_in[5];
    const float* b_lv  = (const float*)d_in[6];
    const float* W_dec = (const float*)d_in[7];
    const float* b_dec = (const float*)d_in[8];

    const int N = in_sizes[1];
    const int D = in_sizes[0] / N;
    const int B = in_sizes[2] / D;
    const int W = in_sizes[4];
    const long k = ((long)out_size - (long)N * D - 1) / ((long)B * (D + 1));

    float* out   = (float*)d_out;
    float* newf  = out;
    float* klp   = out + (size_t)N * D;
    float* ret   = klp + 1;
    float* tidxf = ret + (size_t)B * k * D;

    cudaFuncSetAttribute(k_warm, cudaFuncAttributeMaxDynamicSharedMemorySize, DSMEM_SZ);

    const int gy = (N + 127) / 128;

    // launch order: ncu samples the 4th kernel -> k_sim this round
    k_init<<<1, 1>>>();
    k_partition<<<(N + 255) / 256, 256>>>(tiers, N);
    k_qnorm<<<B, 256>>>(query, D);
    k_sim<<<gy, 256>>>(feats, D, N);

    k_wprep<<<384, 256>>>(W_mu, W_lv, W_dec);
    k_warm<<<gy, 512, DSMEM_SZ>>>(feats, b_mu, b_lv, b_dec, newf);

    long n4 = (long)N * D / 4;
    k_copy4<<<(unsigned)((n4 + 255) / 256), 256>>>((const float4*)feats, (float4*)newf, tiers, n4);

    k_topk<<<B, 256>>>(N, (int)k, tidxf);
    k_gather<<<B * (int)k, 256>>>(newf, ret, D, (int)k);
    k_klfin<<<1, 1>>>(klp, W);
}

// round 10
// speedup vs baseline: 1.5673x; 1.5673x over previous
#include <cuda_runtime.h>
#include <cuda_bf16.h>
#include <math.h>
#include <stdint.h>

// ---------------- static scratch (no allocations allowed) ----------------
#define MAXN 204800
#define MAXB 64

__device__ int    g_warm_idx[MAXN];
__device__ int    g_cold_idx[MAXN];
__device__ int    g_nwarm;
__device__ int    g_ncold;
__device__ double g_kl_sum;
__device__ float  g_sim[(size_t)MAXB * MAXN];
__device__ float  g_qn[MAXB * 256];
__device__ __nv_bfloat16 g_qnb[MAXB * 256];
__device__ float  g_rown[MAXN];          // per-row |x|^2 (all rows)
__device__ int    g_topidx[MAXB * 32];
// pre-converted weights (hi/lo split), [n][k] row-major
__device__ __nv_bfloat16 g_Wh[256 * 256];  // rows 0-127 = W_mu, 128-255 = W_lv
__device__ __nv_bfloat16 g_Wl[256 * 256];
__device__ __nv_bfloat16 g_Dh[256 * 128];  // W_dec
__device__ __nv_bfloat16 g_Dl[256 * 128];

// ---------------- helpers ----------------
__device__ __forceinline__ uint32_t pk2(__nv_bfloat16 a, __nv_bfloat16 b) {
    return (uint32_t)__bfloat16_as_ushort(a) | ((uint32_t)__bfloat16_as_ushort(b) << 16);
}
__device__ __forceinline__ uint32_t smem_u32(const void* p) {
    uint32_t a;
    asm("{ .reg .u64 t; cvta.to.shared.u64 t, %1; cvt.u32.u64 %0, t; }" : "=r"(a) : "l"(p));
    return a;
}

#define MMA16816(c, a, b) asm volatile( \
    "mma.sync.aligned.m16n8k16.row.col.f32.bf16.bf16.f32 " \
    "{%0,%1,%2,%3}, {%4,%5,%6,%7}, {%8,%9}, {%0,%1,%2,%3};" \
    : "+f"((c)[0]), "+f"((c)[1]), "+f"((c)[2]), "+f"((c)[3]) \
    : "r"((a)[0]), "r"((a)[1]), "r"((a)[2]), "r"((a)[3]), "r"((b)[0]), "r"((b)[1]))

__device__ __forceinline__ void ldm4(uint32_t addr, uint32_t r[4]) {
    asm volatile("ldmatrix.sync.aligned.m8n8.x4.shared.b16 {%0,%1,%2,%3}, [%4];"
                 : "=r"(r[0]), "=r"(r[1]), "=r"(r[2]), "=r"(r[3]) : "r"(addr));
}

// smem layout for k_warm (bytes)
#define TSTRIDE 72           // A/B tile stride in bf16
#define MUSTRIDE 136         // mu tile stride in bf16
#define OFF_AH  0
#define OFF_AL  18432
#define OFF_BH  36864
#define OFF_BL  73728
#define OFF_MUH 110592
#define OFF_MUL 145408
#define DSMEM_SZ 180224

__device__ __forceinline__ void split_store4(char* smem, int m, int k, float4 v,
                                             int off_hi, int off_lo) {
    __nv_bfloat16 h0 = __float2bfloat16(v.x), h1 = __float2bfloat16(v.y);
    __nv_bfloat16 h2 = __float2bfloat16(v.z), h3 = __float2bfloat16(v.w);
    float l0 = v.x - __bfloat162float(h0), l1 = v.y - __bfloat162float(h1);
    float l2 = v.z - __bfloat162float(h2), l3 = v.w - __bfloat162float(h3);
    size_t base = (size_t)m * TSTRIDE + k;
    *(uint2*)(smem + off_hi + base * 2) = make_uint2(pk2(h0, h1), pk2(h2, h3));
    *(uint2*)(smem + off_lo + base * 2) =
        make_uint2(pk2(__float2bfloat16(l0), __float2bfloat16(l1)),
                   pk2(__float2bfloat16(l2), __float2bfloat16(l3)));
}

// ---------------- init + query norm (fused) ----------------
__global__ __launch_bounds__(256) void k_initq(const float* __restrict__ q, int D) {
    int b = blockIdx.x, t = threadIdx.x;
    if (b == 0 && t == 0) { g_nwarm = 0; g_ncold = 0; g_kl_sum = 0.0; }
    float ss = 0.f;
    for (int c = t; c < D; c += 256) { float v = q[(size_t)b * D + c]; ss += v * v; }
    __shared__ float red[256];
    red[t] = ss; __syncthreads();
    for (int s = 128; s > 0; s >>= 1) { if (t < s) red[t] += red[t + s]; __syncthreads(); }
    float scale = 1.f / (sqrtf(red[0]) + 1e-10f);
    for (int c = t; c < D; c += 256) {
        float v = q[(size_t)b * D + c] * scale;
        g_qn[(size_t)b * D + c] = v;
        g_qnb[(size_t)b * D + c] = __float2bfloat16(v);
    }
}

// ---------------- warp-aggregated tier partition ----------------
__global__ void k_partition(const int* __restrict__ tiers, int N) {
    int i = blockIdx.x * blockDim.x + threadIdx.x;
    bool in = i < N;
    int t = in ? tiers[i] : 0;
    unsigned m1 = __ballot_sync(0xffffffffu, t == 1);
    unsigned m2 = __ballot_sync(0xffffffffu, t == 2);
    int lane = threadIdx.x & 31;
    unsigned lt = (1u << lane) - 1u;
    if (t == 1) {
        int ldr = __ffs(m1) - 1;
        int base = 0;
        if (lane == ldr) base = atomicAdd(&g_nwarm, __popc(m1));
        base = __shfl_sync(m1, base, ldr);
        g_warm_idx[base + __popc(m1 & lt)] = i;
    } else if (t == 2) {
        int ldr = __ffs(m2) - 1;
        int base = 0;
        if (lane == ldr) base = atomicAdd(&g_ncold, __popc(m2));
        base = __shfl_sync(m2, base, ldr);
        g_cold_idx[base + __popc(m2 & lt)] = i;
    }
}

// ---------------- copy (skip warm) + fused per-row |x|^2 -------------------
// block = 256 threads = 1024 floats = exactly 4 rows (D=256)
__global__ __launch_bounds__(256) void k_copy4(const float4* __restrict__ src,
                                               float4* __restrict__ dst,
                                               const int* __restrict__ tiers, long n4) {
    long i = (long)blockIdx.x * blockDim.x + threadIdx.x;
    int t = threadIdx.x;
    float4 v = make_float4(0.f, 0.f, 0.f, 0.f);
    int row = 0;
    if (i < n4) {
        v = src[i];
        row = (int)(i >> 6);
        if (tiers[row] != 1) dst[i] = v;
    }
    float ss = v.x * v.x + v.y * v.y + v.z * v.z + v.w * v.w;
    #pragma unroll
    for (int o = 16; o > 0; o >>= 1) ss += __shfl_xor_sync(0xffffffffu, ss, o);
    __shared__ float wred[8];
    if ((t & 31) == 0) wred[t >> 5] = ss;
    __syncthreads();
    if (t < 4) {
        long r0 = ((long)blockIdx.x * 256) >> 6;  // first row of block
        if (r0 + t < (n4 >> 6)) g_rown[r0 + t] = wred[2 * t] + wred[2 * t + 1];
    }
}

// ---------------- weight pre-convert ----------------
__global__ __launch_bounds__(256) void k_wprep(const float* __restrict__ W_mu,
                                               const float* __restrict__ W_lv,
                                               const float* __restrict__ W_dec) {
    int idx = blockIdx.x * blockDim.x + threadIdx.x;
    if (idx < 65536) {
        int n = idx >> 8, k = idx & 255;
        float w = (n < 128) ? W_mu[(size_t)n * 256 + k] : W_lv[(size_t)(n - 128) * 256 + k];
        __nv_bfloat16 h = __float2bfloat16(w);
        g_Wh[idx] = h;
        g_Wl[idx] = __float2bfloat16(w - __bfloat162float(h));
    } else if (idx < 65536 + 32768) {
        int j = idx - 65536;
        float w = W_dec[j];
        __nv_bfloat16 h = __float2bfloat16(w);
        g_Dh[j] = h;
        g_Dl[j] = __float2bfloat16(w - __bfloat162float(h));
    }
}

// ---------------- approx sim: single-pass bf16 HMMA ------------------------
// 128 cold rows x 64 queries per block; values only steer candidate selection
// (k_topk rescores in exact fp32), so plain bf16 is sufficient.
__global__ __launch_bounds__(256)
void k_sim(const float* __restrict__ feats, int simld) {
    __shared__ char smem[128 * TSTRIDE * 2 + 64 * TSTRIDE * 2];  // A 18432 + B 9216
    const int OFF_B = 128 * TSTRIDE * 2;
    const int M = g_ncold;
    const int m0 = blockIdx.x * 128;
    if (m0 >= M) return;

    const int tid = threadIdx.x, wid = tid >> 5, lane = tid & 31;
    const int wm = wid >> 1, wn = wid & 1;  // 4x2 warps; warp tile 32 rows x 32 cols
    const uint32_t sb = smem_u32(smem);

    float acc[2][4][4];
    #pragma unroll
    for (int mi = 0; mi < 2; mi++)
        #pragma unroll
        for (int ni = 0; ni < 4; ni++)
            #pragma unroll
            for (int j = 0; j < 4; j++) acc[mi][ni][j] = 0.f;

    const int aRow = (lane & 15), aColSel = (lane >> 4) << 3;
    const int bRow = (lane & 7) + ((lane & 16) >> 1), bColSel = lane & 8;
    const int gq = lane >> 2, qq = (lane & 3) * 2;

    int arows[8];
    #pragma unroll
    for (int it = 0; it < 8; it++) {
        int r = m0 + ((tid + it * 256) >> 4);
        arows[it] = g_cold_idx[(r < M) ? r : m0];
    }

    for (int c = 0; c < 4; c++) {
        const int k0 = c * 64;
        // stage A: 128 rows x 64 cols fp32 -> bf16
        #pragma unroll
        for (int it = 0; it < 8; it++) {
            int id = tid + it * 256;
            int m = id >> 4, kq = id & 15;
            float4 v = *(const float4*)(feats + (size_t)arows[it] * 256 + k0 + kq * 4);
            *(uint2*)(smem + ((size_t)m * TSTRIDE + kq * 4) * 2) =
                make_uint2(pk2(__float2bfloat16(v.x), __float2bfloat16(v.y)),
                           pk2(__float2bfloat16(v.z), __float2bfloat16(v.w)));
        }
        // stage B: queries bf16 copy, 64 rows x 64 cols
        #pragma unroll
        for (int it = 0; it < 2; it++) {
            int id = tid + it * 256;
            int n = id >> 3, u = id & 7;
            *(uint4*)(smem + OFF_B + ((size_t)n * TSTRIDE + u * 8) * 2) =
                *(const uint4*)(g_qnb + (size_t)n * 256 + k0 + u * 8);
        }
        __syncthreads();

        #pragma unroll
        for (int kk = 0; kk < 64; kk += 16) {
            uint32_t a[2][4];
            #pragma unroll
            for (int mi = 0; mi < 2; mi++) {
                uint32_t off = ((uint32_t)(wm * 32 + mi * 16 + aRow) * TSTRIDE + kk + aColSel) * 2;
                ldm4(sb + off, a[mi]);
            }
            #pragma unroll
            for (int np = 0; np < 2; np++) {
                uint32_t boff = ((uint32_t)(wn * 32 + np * 16 + bRow) * TSTRIDE + kk + bColSel) * 2;
                uint32_t bfr[4];
                ldm4(sb + OFF_B + boff, bfr);
                #pragma unroll
                for (int mi = 0; mi < 2; mi++) {
                    MMA16816(acc[mi][np * 2],     a[mi], &bfr[0]);
                    MMA16816(acc[mi][np * 2 + 1], a[mi], &bfr[2]);
                }
            }
        }
        __syncthreads();
    }

    #pragma unroll
    for (int mi = 0; mi < 2; mi++) {
        #pragma unroll
        for (int half = 0; half < 2; half++) {
            int rl = wm * 32 + mi * 16 + gq + half * 8;
            int j = m0 + rl;
            if (j >= M) continue;
            int grown = g_cold_idx[j];
            float inv = 1.f / (sqrtf(g_rown[grown]) + 1e-10f);
            #pragma unroll
            for (int ni = 0; ni < 4; ni++) {
                int q = wn * 32 + ni * 8 + qq;
                g_sim[(size_t)q * simld + j] = acc[mi][ni][half * 2 + 0] * inv;
                g_sim[(size_t)(q + 1) * simld + j] = acc[mi][ni][half * 2 + 1] * inv;
            }
        }
    }
}

// ---------------- fused warm pipeline (as R7 + lv single-pass, no prefetch) -
__global__ __launch_bounds__(512)
void k_warm(const float* __restrict__ feats,
            const float* __restrict__ b_mu, const float* __restrict__ b_lv,
            const float* __restrict__ b_dec, float* __restrict__ newf) {
    extern __shared__ char smem[];
    const int M = g_nwarm;
    const int m0 = blockIdx.x * 128;
    if (m0 >= M) return;

    const int tid = threadIdx.x, wid = tid >> 5, lane = tid & 31;
    const int wm = wid >> 2, wn = wid & 3;
    const bool is_mu_warp = (wn < 2);
    const uint32_t sb = smem_u32(smem);

    float acc[2][8][4];
    #pragma unroll
    for (int mi = 0; mi < 2; mi++)
        #pragma unroll
        for (int ni = 0; ni < 8; ni++)
            #pragma unroll
            for (int j = 0; j < 4; j++) acc[mi][ni][j] = 0.f;

    const int aRow = (lane & 15), aColSel = (lane >> 4) << 3;
    const int bRow = (lane & 7) + ((lane & 16) >> 1), bColSel = lane & 8;
    const int gq = lane >> 2, qq = (lane & 3) * 2;

    int arows[4];
    #pragma unroll
    for (int it = 0; it < 4; it++) {
        int r = m0 + ((tid + it * 512) >> 4);
        arows[it] = g_warm_idx[(r < M) ? r : m0];
    }

    for (int c = 0; c < 4; c++) {
        const int k0 = c * 64;
        #pragma unroll
        for (int it = 0; it < 4; it++) {
            int id = tid + it * 512;
            float4 v = *(const float4*)(feats + (size_t)arows[it] * 256 + k0 + (id & 15) * 4);
            split_store4(smem, id >> 4, (id & 15) * 4, v, OFF_AH, OFF_AL);
        }
        #pragma unroll
        for (int it = 0; it < 4; it++) {
            int id = tid + it * 512;
            int n = id >> 3, q = id & 7;
            size_t src = (size_t)n * 256 + k0 + q * 8;
            size_t dst = ((size_t)n * TSTRIDE + q * 8) * 2;
            *(uint4*)(smem + OFF_BH + dst) = *(const uint4*)(g_Wh + src);
            *(uint4*)(smem + OFF_BL + dst) = *(const uint4*)(g_Wl + src);
        }
        __syncthreads();

        #pragma unroll
        for (int kk = 0; kk < 64; kk += 16) {
            uint32_t ah[2][4], al[2][4];
            #pragma unroll
            for (int mi = 0; mi < 2; mi++) {
                uint32_t off = ((uint32_t)(wm * 32 + mi * 16 + aRow) * TSTRIDE + kk + aColSel) * 2;
                ldm4(sb + OFF_AH + off, ah[mi]);
                if (is_mu_warp) ldm4(sb + OFF_AL + off, al[mi]);
            }
            #pragma unroll
            for (int np = 0; np < 4; np++) {
                int n0 = wn * 64 + np * 16;
                uint32_t boff = ((uint32_t)(n0 + bRow) * TSTRIDE + kk + bColSel) * 2;
                uint32_t bh[4], bl[4];
                ldm4(sb + OFF_BH + boff, bh);
                if (is_mu_warp) ldm4(sb + OFF_BL + boff, bl);
                #pragma unroll
                for (int mi = 0; mi < 2; mi++) {
                    MMA16816(acc[mi][np * 2],     ah[mi], &bh[0]);
                    MMA16816(acc[mi][np * 2 + 1], ah[mi], &bh[2]);
                    if (is_mu_warp) {
                        MMA16816(acc[mi][np * 2],     al[mi], &bh[0]);
                        MMA16816(acc[mi][np * 2],     ah[mi], &bl[0]);
                        MMA16816(acc[mi][np * 2 + 1], al[mi], &bh[2]);
                        MMA16816(acc[mi][np * 2 + 1], ah[mi], &bl[2]);
                    }
                }
            }
        }
        __syncthreads();
    }

    float kl = 0.f;
    #pragma unroll
    for (int mi = 0; mi < 2; mi++) {
        #pragma unroll
        for (int half = 0; half < 2; half++) {
            int rl = wm * 32 + mi * 16 + gq + half * 8;
            int grow = m0 + rl;
            bool valid = grow < M;
            #pragma unroll
            for (int ni = 0; ni < 8; ni++) {
                int col = wn * 64 + ni * 8 + qq;
                int is_lv = col >> 7;
                int cl = col & 127;
                float bias0 = is_lv ? b_lv[cl] : b_mu[cl];
                float bias1 = is_lv ? b_lv[cl + 1] : b_mu[cl + 1];
                float v0 = acc[mi][ni][half * 2 + 0] + bias0;
                float v1 = acc[mi][ni][half * 2 + 1] + bias1;
                if (!is_lv) {
                    __nv_bfloat16 h0 = __float2bfloat16(v0), h1 = __float2bfloat16(v1);
                    float l0 = v0 - __bfloat162float(h0), l1 = v1 - __bfloat162float(h1);
                    uint32_t o = ((uint32_t)rl * MUSTRIDE + cl) * 2;
                    *(uint32_t*)(smem + OFF_MUH + o) = pk2(h0, h1);
                    *(uint32_t*)(smem + OFF_MUL + o) = pk2(__float2bfloat16(l0), __float2bfloat16(l1));
                    if (valid) kl += 0.5f * (v0 * v0 + v1 * v1) - 1.0f;
                } else if (valid) {
                    kl += 0.5f * (expf(v0) + expf(v1)) - 0.5f * (v0 + v1);
                }
            }
        }
    }
    #pragma unroll
    for (int o = 16; o > 0; o >>= 1) kl += __shfl_xor_sync(0xffffffffu, kl, o);
    if (lane == 0 && kl != 0.f) atomicAdd(&g_kl_sum, (double)kl);
    __syncthreads();

    #pragma unroll
    for (int mi = 0; mi < 2; mi++)
        #pragma unroll
        for (int ni = 0; ni < 8; ni++)
            #pragma unroll
            for (int j = 0; j < 4; j++) acc[mi][ni][j] = 0.f;

    for (int c = 0; c < 2; c++) {
        const int k0 = c * 64;
        #pragma unroll
        for (int it = 0; it < 4; it++) {
            int id = tid + it * 512;
            int n = id >> 3, q = id & 7;
            size_t src = (size_t)n * 128 + k0 + q * 8;
            size_t dst = ((size_t)n * TSTRIDE + q * 8) * 2;
            *(uint4*)(smem + OFF_BH + dst) = *(const uint4*)(g_Dh + src);
            *(uint4*)(smem + OFF_BL + dst) = *(const uint4*)(g_Dl + src);
        }
        __syncthreads();

        #pragma unroll
        for (int kk = 0; kk < 64; kk += 16) {
            uint32_t ah[2][4], al[2][4];
            #pragma unroll
            for (int mi = 0; mi < 2; mi++) {
                uint32_t off = ((uint32_t)(wm * 32 + mi * 16 + aRow) * MUSTRIDE + k0 + kk + aColSel) * 2;
                ldm4(sb + OFF_MUH + off, ah[mi]);
                ldm4(sb + OFF_MUL + off, al[mi]);
            }
            #pragma unroll
            for (int np = 0; np < 4; np++) {
                int n0 = wn * 64 + np * 16;
                uint32_t boff = ((uint32_t)(n0 + bRow) * TSTRIDE + kk + bColSel) * 2;
                uint32_t bh[4], bl[4];
                ldm4(sb + OFF_BH + boff, bh);
                ldm4(sb + OFF_BL + boff, bl);
                #pragma unroll
                for (int mi = 0; mi < 2; mi++) {
                    MMA16816(acc[mi][np * 2],     ah[mi], &bh[0]);
                    MMA16816(acc[mi][np * 2],     al[mi], &bh[0]);
                    MMA16816(acc[mi][np * 2],     ah[mi], &bl[0]);
                    MMA16816(acc[mi][np * 2 + 1], ah[mi], &bh[2]);
                    MMA16816(acc[mi][np * 2 + 1], al[mi], &bh[2]);
                    MMA16816(acc[mi][np * 2 + 1], ah[mi], &bl[2]);
                }
            }
        }
        __syncthreads();
    }

    #pragma unroll
    for (int mi = 0; mi < 2; mi++) {
        #pragma unroll
        for (int half = 0; half < 2; half++) {
            int grow = m0 + wm * 32 + mi * 16 + gq + half * 8;
            if (grow >= M) continue;
            int wr = g_warm_idx[grow];
            #pragma unroll
            for (int ni = 0; ni < 8; ni++) {
                int col = wn * 64 + ni * 8 + qq;
                float2 v = make_float2(acc[mi][ni][half * 2 + 0] + b_dec[col],
                                       acc[mi][ni][half * 2 + 1] + b_dec[col + 1]);
                *(float2*)(newf + (size_t)wr * 256 + col) = v;
            }
        }
    }
}

// ---------------- top-k: approx top-32 -> exact fp32 rescore ---------------
__global__ __launch_bounds__(256) void k_topk(const float* __restrict__ feats,
                                              int simld, int k,
                                              float* __restrict__ out_idx_f) {
    const int b = blockIdx.x;
    const int ncold = g_ncold;
    const int t = threadIdx.x;

    float tv[4]; int tg[4];
    #pragma unroll
    for (int s = 0; s < 4; s++) { tv[s] = -INFINITY; tg[s] = 0x7fffffff; }

    const float* srow = g_sim + (size_t)b * simld;
    for (int j = t; j < ncold; j += 256) {
        float v = srow[j];
        if (v > tv[3]) {
            int g = g_cold_idx[j];
            tv[3] = v; tg[3] = g;
            #pragma unroll
            for (int s = 2; s >= 0; s--) {
                if (tv[s + 1] > tv[s]) {
                    float x = tv[s]; tv[s] = tv[s + 1]; tv[s + 1] = x;
                    int y = tg[s]; tg[s] = tg[s + 1]; tg[s + 1] = y;
                }
            }
        }
    }

    __shared__ float sval[1024];
    __shared__ int   sgid[1024];
    __shared__ float rv[256];
    __shared__ int   ri[256];
    __shared__ int   rp[256];
    __shared__ int   cgid[32];
    __shared__ float rsv[32];

    #pragma unroll
    for (int s = 0; s < 4; s++) { sval[t * 4 + s] = tv[s]; sgid[t * 4 + s] = tg[s]; }
    __syncthreads();

    // select 32 approx-best (value desc, idx asc)
    for (int sel = 0; sel < 32; sel++) {
        float bv = -INFINITY; int bi = 0x7fffffff; int bp = -1;
        #pragma unroll
        for (int u = 0; u < 4; u++) {
            int p = t + u * 256;
            float v = sval[p]; int gi = sgid[p];
            if (v > bv || (v == bv && gi < bi)) { bv = v; bi = gi; bp = p; }
        }
        rv[t] = bv; ri[t] = bi; rp[t] = bp;
        __syncthreads();
        for (int s = 128; s > 0; s >>= 1) {
            if (t < s) {
                if (rv[t + s] > rv[t] || (rv[t + s] == rv[t] && ri[t + s] < ri[t])) {
                    rv[t] = rv[t + s]; ri[t] = ri[t + s]; rp[t] = rp[t + s];
                }
            }
            __syncthreads();
        }
        if (t == 0) {
            cgid[sel] = ri[0];
            if (rp[0] >= 0) { sval[rp[0]] = -INFINITY; sgid[rp[0]] = 0x7fffffff; }
        }
        __syncthreads();
    }

    // exact fp32 rescore of the 32 candidates (8 threads per candidate)
    {
        int c = t >> 3, e = t & 7;
        int g = cgid[c];
        float part = 0.f;
        if (g != 0x7fffffff) {
            const float* fr = feats + (size_t)g * 256 + e * 32;
            const float* qr = g_qn + (size_t)b * 256 + e * 32;
            #pragma unroll
            for (int x = 0; x < 32; x += 4) {
                float4 f = *(const float4*)(fr + x);
                float4 qv = *(const float4*)(qr + x);
                part += f.x * qv.x + f.y * qv.y + f.z * qv.z + f.w * qv.w;
            }
        }
        #pragma unroll
        for (int o = 4; o > 0; o >>= 1) part += __shfl_xor_sync(0xffffffffu, part, o);
        if (e == 0)
            rsv[c] = (g != 0x7fffffff)
                   ? part / (sqrtf(g_rown[g]) + 1e-10f) : -INFINITY;
    }
    __syncthreads();

    // rank the 32 exactly (value desc, idx asc) and emit top-k
    if (t < 32) {
        float v = rsv[t]; int g = cgid[t];
        int rank = 0;
        #pragma unroll
        for (int j2 = 0; j2 < 32; j2++) {
            float vj = rsv[j2]; int gj = cgid[j2];
            if (vj > v || (vj == v && gj < g)) rank++;
        }
        if (rank < k) {
            g_topidx[b * 32 + rank] = g;
            out_idx_f[(size_t)b * k + rank] = (float)g;
        }
    }
}

// ---------------- gather + kl finalize ----------------
__global__ __launch_bounds__(256) void k_gather(const float* __restrict__ newf,
                                                float* __restrict__ ret, int D, int k,
                                                float* __restrict__ klp, int W) {
    int r = blockIdx.x;
    if (r == 0 && threadIdx.x == 0) {
        int n = g_nwarm > 0 ? g_nwarm : 1;
        *klp = (float)(g_kl_sum / ((double)n * (double)W));
    }
    int row = g_topidx[(r / k) * 32 + (r % k)];
    const float* s = newf + (size_t)row * D;
    float* d = ret + (size_t)r * D;
    for (int c = threadIdx.x; c < D; c += blockDim.x) d[c] = s[c];
}

extern "C" void kernel_launch(void* const* d_in, const int* in_sizes, int n_in,
                              void* d_out, int out_size) {
    const float* feats = (const float*)d_in[0];
    const int*   tiers = (const int*)d_in[1];
    const float* query = (const float*)d_in[2];
    const float* W_mu  = (const float*)d_in[3];
    const float* b_mu  = (const float*)d_in[4];
    const float* W_lv  = (const float*)d_in[5];
    const float* b_lv  = (const float*)d_in[6];
    const float* W_dec = (const float*)d_in[7];
    const float* b_dec = (const float*)d_in[8];

    const int N = in_sizes[1];
    const int D = in_sizes[0] / N;
    const int B = in_sizes[2] / D;
    const int W = in_sizes[4];
    const long k = ((long)out_size - (long)N * D - 1) / ((long)B * (D + 1));

    float* out   = (float*)d_out;
    float* newf  = out;
    float* klp   = out + (size_t)N * D;
    float* ret   = klp + 1;
    float* tidxf = ret + (size_t)B * k * D;

    cudaFuncSetAttribute(k_warm, cudaFuncAttributeMaxDynamicSharedMemorySize, DSMEM_SZ);

    const int gy = (N + 127) / 128;
    long n4 = (long)N * D / 4;

    // order: k_sim is the 4th launch -> profiled by ncu (-s 5 -c 1)
    k_initq<<<B, 256>>>(query, D);
    k_partition<<<(N + 255) / 256, 256>>>(tiers, N);
    k_copy4<<<(unsigned)((n4 + 255) / 256), 256>>>((const float4*)feats, (float4*)newf, tiers, n4);
    k_sim<<<gy, 256>>>(feats, N);

    k_wprep<<<384, 256>>>(W_mu, W_lv, W_dec);
    k_warm<<<gy, 512, DSMEM_SZ>>>(feats, b_mu, b_lv, b_dec, newf);

    k_topk<<<B, 256>>>(feats, N, (int)k, tidxf);
    k_gather<<<B * (int)k, 256>>>(newf, ret, D, (int)k, klp, W);
}